// round 7
// baseline (speedup 1.0000x reference)
#include <cuda_runtime.h>
#include <cuda_bf16.h>
#include <math.h>
#include <stdint.h>

#define BB 64
#define QQ 1000
#define DD 512
#define CC 81
#define NK 80
#define KB 5
#define MK 5
#define BQ 64000          // BB*QQ
#define JJ 400            // NK*KB boundary slots per batch
#define DELTA 0.6f
#define INVALID_IDX 0x7fffffff

// ---------------- scratch (device globals; no allocations allowed) ----------------
__device__ uint4 g_embn4[(size_t)BQ * (DD / 8)];     // normalized embeddings, bf16 (65.5 MB)
__device__ uint4 g_protonb4[CC * (DD / 8)];          // normalized prototypes, bf16
__device__ float g_dist2[BQ];
__device__ float g_proto_n[CC * DD];                 // normalized prototypes fp32 (k_pneg)
__device__ float g_p2[NK];
__device__ float g_pinv[CC];
__device__ int   g_mlist[BQ];
__device__ int   g_mcnt;
__device__ int   g_ulist[BB * 1024];
__device__ int   g_ucnt[BB];
__device__ int   g_bnd_gemm[BB * JJ];
__device__ unsigned char g_bnd_valid[BB * JJ];
__device__ int   g_nb[BB * JJ * MK];
__device__ int   g_nbcnt[BB * JJ];
__device__ unsigned char g_sgv[BB * JJ];
__device__ float g_Sm[(size_t)BQ * CC];              // exp(S) for matched rows (20.7 MB)
__device__ float g_posexp[BQ];                       // fp32-exact pos exp, per row n
__device__ float g_colsum[CC];
__device__ float g_possum[CC];
__device__ float g_pneg[CC];
__device__ double g_sul_sum;
__device__ double g_cec_sum;
__device__ int    g_nsg;

// ---------------- helpers ----------------
__device__ __forceinline__ uint32_t smem_u32(const void* p) {
    uint32_t a;
    asm("{ .reg .u64 t; cvta.to.shared.u64 t, %1; cvt.u32.u64 %0, t; }" : "=r"(a) : "l"(p));
    return a;
}
__device__ __forceinline__ void ldsm_x4(uint32_t& r0, uint32_t& r1, uint32_t& r2, uint32_t& r3,
                                        uint32_t addr) {
    asm volatile("ldmatrix.sync.aligned.m8n8.x4.shared.b16 {%0,%1,%2,%3}, [%4];"
                 : "=r"(r0), "=r"(r1), "=r"(r2), "=r"(r3) : "r"(addr));
}
__device__ __forceinline__ void mma_16816(float* c, const uint32_t* a, uint32_t b0, uint32_t b1) {
    asm volatile(
        "mma.sync.aligned.m16n8k16.row.col.f32.bf16.bf16.f32 "
        "{%0,%1,%2,%3}, {%4,%5,%6,%7}, {%8,%9}, {%0,%1,%2,%3};"
        : "+f"(c[0]), "+f"(c[1]), "+f"(c[2]), "+f"(c[3])
        : "r"(a[0]), "r"(a[1]), "r"(a[2]), "r"(a[3]), "r"(b0), "r"(b1));
}
#define CP16(sm, gm) asm volatile("cp.async.cg.shared.global [%0], [%1], 16;" :: "r"(sm), "l"(gm))
#define CP_COMMIT()  asm volatile("cp.async.commit_group;" ::: "memory")
#define CP_WAIT0()   asm volatile("cp.async.wait_group 0;" ::: "memory")
#define CP_WAIT1()   asm volatile("cp.async.wait_group 1;" ::: "memory")

// ---------------- warp-cooperative top-5 (stable: value desc, index asc) ----------------
__device__ __forceinline__ void lane_ins5(float* v, int* ix, float s, int q) {
    if (s <= v[4]) return;
    int p = 4;
#pragma unroll
    for (int j = 3; j >= 0; j--) if (s > v[j]) p = j;
#pragma unroll
    for (int j = 4; j > 0; j--) if (j > p) { v[j] = v[j - 1]; ix[j] = ix[j - 1]; }
    v[p] = s; ix[p] = q;
}
__device__ __forceinline__ void warp_merge5(float* v, int* ix, float* ov, int* oi) {
#pragma unroll
    for (int r = 0; r < 5; r++) {
        float bv = v[0]; int bi = ix[0];
#pragma unroll
        for (int o = 16; o; o >>= 1) {
            float tv = __shfl_xor_sync(0xffffffffu, bv, o);
            int   ti = __shfl_xor_sync(0xffffffffu, bi, o);
            if (tv > bv || (tv == bv && ti < bi)) { bv = tv; bi = ti; }
        }
        ov[r] = bv; oi[r] = bi;
        if (ix[0] == bi && bi != INVALID_IDX) {
#pragma unroll
            for (int j = 0; j < 4; j++) { v[j] = v[j + 1]; ix[j] = ix[j + 1]; }
            v[4] = -INFINITY; ix[4] = INVALID_IDX;
        }
    }
}

// ---------------- kernels ----------------
__global__ void k_init() {
    int t = threadIdx.x;
    if (t == 0) { g_mcnt = 0; g_nsg = 0; g_sul_sum = 0.0; g_cec_sum = 0.0; }
    if (t < BB) g_ucnt[t] = 0;
    if (t < CC) { g_colsum[t] = 0.0f; g_possum[t] = 0.0f; }
}

__global__ void k_proto(const float* __restrict__ protos) {
    int c = blockIdx.x, t = threadIdx.x;
    const float* row = protos + (size_t)c * DD;
    float s = 0.0f;
    for (int i = t; i < DD; i += 128) { float v = row[i]; s += v * v; }
    for (int o = 16; o; o >>= 1) s += __shfl_xor_sync(0xffffffffu, s, o);
    __shared__ float ws[4];
    if ((t & 31) == 0) ws[t >> 5] = s;
    __syncthreads();
    __shared__ float sinv;
    if (t == 0) {
        float tot = ws[0] + ws[1] + ws[2] + ws[3];
        if (c < NK) g_p2[c] = tot;
        float inv = 1.0f / fmaxf(sqrtf(tot), 1e-12f);
        g_pinv[c] = inv;
        sinv = inv;
    }
    __syncthreads();
    float inv = sinv;
    const float2* r2 = (const float2*)row;
    uint32_t* pb = (uint32_t*)g_protonb4 + c * (DD / 2);
    for (int i = t; i < DD / 2; i += 128) {
        float2 f = r2[i];
        float x = f.x * inv, y = f.y * inv;
        g_proto_n[c * DD + 2 * i] = x;
        g_proto_n[c * DD + 2 * i + 1] = y;
        __nv_bfloat162 h = __floats2bfloat162_rn(x, y);
        pb[i] = *(uint32_t*)&h;
    }
}

// warp per row: norm, bf16 normalized copy, matched dist + exact fp32 pos_exp, compaction
__global__ void k_rows(const float* __restrict__ obj, const int* __restrict__ labels,
                       const float* __restrict__ protos) {
    int gw = (blockIdx.x * blockDim.x + threadIdx.x) >> 5;
    int lane = threadIdx.x & 31;
    if (gw >= BQ) return;
    const float2* row = (const float2*)(obj + (size_t)gw * DD);
    float2 v[8];
    float s = 0.0f;
#pragma unroll
    for (int i = 0; i < 8; i++) { v[i] = row[lane + 32 * i]; s += v[i].x * v[i].x + v[i].y * v[i].y; }
#pragma unroll
    for (int o = 16; o; o >>= 1) s += __shfl_xor_sync(0xffffffffu, s, o);
    float inv = 1.0f / fmaxf(sqrtf(s), 1e-12f);
    uint32_t* eb = (uint32_t*)g_embn4 + (size_t)gw * (DD / 2);
#pragma unroll
    for (int i = 0; i < 8; i++) {
        __nv_bfloat162 h = __floats2bfloat162_rn(v[i].x * inv, v[i].y * inv);
        eb[lane + 32 * i] = *(uint32_t*)&h;
    }
    int lab = labels[gw];
    if (lab < NK) {
        const float2* pr = (const float2*)(protos + (size_t)lab * DD);
        float d = 0.0f;
#pragma unroll
        for (int i = 0; i < 8; i++) { float2 p = pr[lane + 32 * i]; d += v[i].x * p.x + v[i].y * p.y; }
#pragma unroll
        for (int o = 16; o; o >>= 1) d += __shfl_xor_sync(0xffffffffu, d, o);
        if (lane == 0) {
            g_dist2[gw] = s - 2.0f * d + g_p2[lab];
            g_posexp[gw] = expf(d * inv * g_pinv[lab] * 10.0f);   // exact fp32 S_pos
            int slot = atomicAdd(&g_mcnt, 1);
            g_mlist[slot] = gw;
        }
    } else if (lane == 0) {
        int b = gw / QQ;
        int slot = atomicAdd(&g_ucnt[b], 1);
        g_ulist[b * 1024 + slot] = gw;
    }
}

// warp per (b,k): top-5 matched distances; int4 label loads
__global__ void k_bnd(const int* __restrict__ labels) {
    int gw = (blockIdx.x * blockDim.x + threadIdx.x) >> 5;
    int lane = threadIdx.x & 31;
    if (gw >= BB * NK) return;
    int b = gw / NK, k = gw - b * NK;
    const int4* lb4 = (const int4*)(labels + b * QQ);   // 250 int4s
    const float* dd = g_dist2 + b * QQ;
    float v[5] = {-INFINITY, -INFINITY, -INFINITY, -INFINITY, -INFINITY};
    int ix[5] = {INVALID_IDX, INVALID_IDX, INVALID_IDX, INVALID_IDX, INVALID_IDX};
#pragma unroll
    for (int p = 0; p < 8; p++) {
        int q4 = lane + p * 32;
        if (q4 < 250) {
            int4 L = lb4[q4];
            int qb = q4 * 4;
            if (L.x == k) lane_ins5(v, ix, dd[qb], qb);
            if (L.y == k) lane_ins5(v, ix, dd[qb + 1], qb + 1);
            if (L.z == k) lane_ins5(v, ix, dd[qb + 2], qb + 2);
            if (L.w == k) lane_ins5(v, ix, dd[qb + 3], qb + 3);
        }
    }
    float ov[5]; int oi[5];
    warp_merge5(v, ix, ov, oi);
    if (lane == 0) {
        int base = gw * KB;
#pragma unroll
        for (int i = 0; i < 5; i++) {
            bool valid = oi[i] != INVALID_IDX;
            g_bnd_valid[base + i] = valid ? 1 : 0;
            g_bnd_gemm[base + i] = b * QQ + (valid ? oi[i] : 0);
        }
    }
}

// ---------------- bf16 HMMA gather-GEMM, double-buffered cp.async, fused epilogue ----------
// mode 0: per (z=batch, m-tile) CTA loops all u-chunks; running top-5 per row in smem;
//         writes g_nb / g_nbcnt / g_sgv directly (no SIM matrix materialized).
// mode 1: Sm[m][c] = exp(10*<embn[mlist], proton>), loops 2 chunks, direct store.
//
// smem layout (bytes):
//   0     aid[128]           512
//   512   bid[64]            256
//   1024  A0 128x144         18432
//   19456 B0 64x144          9216
//   28672 A1                 18432
//   47104 B1                 9216
//   [epilogue transpose sD: float[128][66] aliased at 1024 (buffers idle)]
//   56320 top5 val float[128*5]  2560
//   58880 top5 idx int[128*5]    2560
//   total 61440
#define ASTRIDE 144
#define BUFSTRIDE 27648
#define SMEM_TOTAL_TG 61440

__device__ __forceinline__ void tg_prefetch(uint32_t sbase, int buf, int ch,
                                            const uint4* __restrict__ Asrc,
                                            const uint4* __restrict__ Bsrc,
                                            const int* aid, const int* bid, int tid) {
    uint32_t Ab = sbase + 1024 + buf * BUFSTRIDE;
    uint32_t Bb = sbase + 19456 + buf * BUFSTRIDE;
#pragma unroll
    for (int i = 0; i < 4; i++) {
        int idx = tid + i * 256, r = idx >> 3, j = idx & 7;
        CP16(Ab + r * ASTRIDE + j * 16, Asrc + (size_t)aid[r] * 64 + ch * 8 + j);
    }
#pragma unroll
    for (int i = 0; i < 2; i++) {
        int idx = tid + i * 256, r = idx >> 3, j = idx & 7;
        CP16(Bb + r * ASTRIDE + j * 16, Bsrc + (size_t)bid[r] * 64 + ch * 8 + j);
    }
    CP_COMMIT();
}

__global__ void __launch_bounds__(256) k_tgemm(int mode) {
    extern __shared__ unsigned char smem[];
    const int tid = threadIdx.x, wid = tid >> 5, lid = tid & 31;
    const int wm = wid & 3, wn = wid >> 2;
    const int z = blockIdx.z;
    const int m0 = blockIdx.x * 128;
    int M, NY, U = 0;
    const uint4 *Asrc, *Bsrc;
    if (mode == 0) {
        M = JJ; U = g_ucnt[z]; NY = (U + 63) >> 6;
        Asrc = g_embn4; Bsrc = g_embn4;
    } else {
        M = g_mcnt;
        if (m0 >= M) return;
        NY = 2;
        Asrc = g_embn4; Bsrc = g_protonb4;
    }
    int* aid = (int*)smem;
    int* bid = (int*)(smem + 512);
    float* v5 = (float*)(smem + 56320);
    int*   i5 = (int*)(smem + 58880);
    uint32_t sbase = smem_u32(smem);
    if (tid < 128) {
        int r = m0 + tid;
        int a;
        if (mode == 0) a = g_bnd_gemm[z * JJ + (r < JJ ? r : 0)];
        else a = (r < M) ? g_mlist[r] : g_mlist[0];
        aid[tid] = a;
    }
    if (mode == 0) {
        for (int i = tid; i < 640; i += 256) { v5[i] = -INFINITY; i5[i] = INVALID_IDX; }
    }

    // per-lane ldmatrix address components (buffer 0 base; add buf*BUFSTRIDE)
    const uint32_t As0 = sbase + 1024, Bs0 = sbase + 19456;
    uint32_t aAddr = As0 + (uint32_t)(wm * 32 + (lid & 15)) * ASTRIDE + ((lid >> 4) * 8) * 2;
    uint32_t bAddr = Bs0 + (uint32_t)(wn * 32 + ((lid & 7) | ((lid >> 4) << 3))) * ASTRIDE
                         + (((lid >> 3) & 1) * 8) * 2;

    for (int y = 0; y < NY; y++) {
        if (tid < 64) {
            int c = y * 64 + tid, b0;
            if (mode == 0) b0 = (c < U) ? g_ulist[z * 1024 + c] : g_ulist[z * 1024];
            else b0 = (c < CC) ? c : 0;
            bid[tid] = b0;
        }
        __syncthreads();   // bid visible; prior epilogue's smem reads done

        float acc[2][4][4];
#pragma unroll
        for (int i = 0; i < 2; i++)
#pragma unroll
            for (int j = 0; j < 4; j++)
#pragma unroll
                for (int e = 0; e < 4; e++) acc[i][j][e] = 0.0f;

        int buf = 0;
        tg_prefetch(sbase, 0, 0, Asrc, Bsrc, aid, bid, tid);
        for (int ch = 0; ch < 8; ch++) {
            if (ch < 7) tg_prefetch(sbase, buf ^ 1, ch + 1, Asrc, Bsrc, aid, bid, tid);
            if (ch < 7) CP_WAIT1(); else CP_WAIT0();
            __syncthreads();
            uint32_t aA = aAddr + buf * BUFSTRIDE, bA = bAddr + buf * BUFSTRIDE;
#pragma unroll
            for (int ks = 0; ks < 4; ks++) {
                uint32_t a[2][4], b[2][4];
#pragma unroll
                for (int mt = 0; mt < 2; mt++)
                    ldsm_x4(a[mt][0], a[mt][1], a[mt][2], a[mt][3],
                            aA + mt * 16 * ASTRIDE + ks * 32);
#pragma unroll
                for (int nh = 0; nh < 2; nh++)
                    ldsm_x4(b[nh][0], b[nh][1], b[nh][2], b[nh][3],
                            bA + nh * 16 * ASTRIDE + ks * 32);
#pragma unroll
                for (int mt = 0; mt < 2; mt++)
#pragma unroll
                    for (int nt = 0; nt < 4; nt++) {
                        int nh = nt >> 1, hi = (nt & 1) << 1;
                        mma_16816(acc[mt][nt], a[mt], b[nh][hi], b[nh][hi + 1]);
                    }
            }
            __syncthreads();
            buf ^= 1;
        }

        if (mode == 0) {
            // transpose acc -> sD (aliases idle buffers)
            float* sD = (float*)(smem + 1024);   // 128 x 66
#pragma unroll
            for (int mt = 0; mt < 2; mt++)
#pragma unroll
                for (int nt = 0; nt < 4; nt++)
#pragma unroll
                    for (int e = 0; e < 4; e++) {
                        int row = wm * 32 + mt * 16 + (lid >> 2) + ((e >> 1) << 3);
                        int col = wn * 32 + nt * 8 + (lid & 3) * 2 + (e & 1);
                        sD[row * 66 + col] = acc[mt][nt][e];
                    }
            __syncthreads();
            // warp wid handles rows wid*16 .. +15: merge chunk top-5 into running
            for (int rr = 0; rr < 16; rr++) {
                int r = wid * 16 + rr;
                float va = sD[r * 66 + lid * 2];
                float vb = sD[r * 66 + lid * 2 + 1];
                int ua = y * 64 + lid * 2, ub = ua + 1;
                if (ua >= U) va = -INFINITY;
                if (ub >= U) vb = -INFINITY;
                float top[5]; int tix[5];
#pragma unroll
                for (int round = 0; round < 5; round++) {
                    float bv; int bi;
                    if (vb > va) { bv = vb; bi = ub; } else { bv = va; bi = ua; }
#pragma unroll
                    for (int o = 16; o; o >>= 1) {
                        float tv = __shfl_xor_sync(0xffffffffu, bv, o);
                        int   ti = __shfl_xor_sync(0xffffffffu, bi, o);
                        if (tv > bv || (tv == bv && ti < bi)) { bv = tv; bi = ti; }
                    }
                    if (bv == -INFINITY) bi = INVALID_IDX;
                    top[round] = bv; tix[round] = bi;
                    if (ua == bi) va = -INFINITY;
                    if (ub == bi) vb = -INFINITY;
                }
                if (lid == 0) {
                    float rv[5]; int ri[5], a = 0, bix = 0;
#pragma unroll
                    for (int i = 0; i < 5; i++) { rv[i] = v5[r * 5 + i]; ri[i] = i5[r * 5 + i]; }
                    float nv[5]; int ni[5];
#pragma unroll
                    for (int s = 0; s < 5; s++) {
                        bool takeR = (rv[a] > top[bix]) ||
                                     (rv[a] == top[bix] && ri[a] <= tix[bix]);
                        if (takeR) { nv[s] = rv[a]; ni[s] = ri[a]; a++; }
                        else       { nv[s] = top[bix]; ni[s] = tix[bix]; bix++; }
                    }
#pragma unroll
                    for (int i = 0; i < 5; i++) { v5[r * 5 + i] = nv[i]; i5[r * 5 + i] = ni[i]; }
                }
            }
            __syncthreads();
        } else {
#pragma unroll
            for (int mt = 0; mt < 2; mt++)
#pragma unroll
                for (int nt = 0; nt < 4; nt++)
#pragma unroll
                    for (int e = 0; e < 4; e++) {
                        int gr = m0 + wm * 32 + mt * 16 + (lid >> 2) + ((e >> 1) << 3);
                        int col = y * 64 + wn * 32 + nt * 8 + (lid & 3) * 2 + (e & 1);
                        if (gr < M && col < CC)
                            g_Sm[(size_t)gr * CC + col] = expf(acc[mt][nt][e] * 10.0f);
                    }
            __syncthreads();
        }
    }

    if (mode == 0) {
        // final per-row writes (handles NY==0 too: cnt=0)
        if (tid < 128) {
            int gr = m0 + tid;
            if (gr < JJ) {
                int bj = z * JJ + gr;
                int cnt = 0;
                int* nb = g_nb + bj * MK;
#pragma unroll
                for (int i = 0; i < 5; i++) {
                    float vv = v5[tid * 5 + i];
                    int   ii = i5[tid * 5 + i];
                    bool valid = ii != INVALID_IDX;
                    cnt += (valid && vv > DELTA) ? 1 : 0;
                    nb[i] = valid ? g_ulist[z * 1024 + ii] : -1;
                }
                g_nbcnt[bj] = cnt;
                g_sgv[bj] = (g_bnd_valid[bj] && cnt > 0) ? 1 : 0;
            }
        }
    }
}

// gated: g_bar -> logits -> CE (expected: no valid slots -> no work)
__global__ void k_ce(const float* __restrict__ obj, const float* __restrict__ cls_w,
                     const float* __restrict__ cls_b) {
    int bj = blockIdx.x;
    if (!g_sgv[bj]) return;
    int t = threadIdx.x;
    __shared__ float gb[DD];
    __shared__ float lg[CC];
    int cnt = g_nbcnt[bj];
    float idn = 1.0f / (1.0f + (float)cnt);
    const int* nb = g_nb + bj * MK;
    int bnd = g_bnd_gemm[bj];
    for (int d = t; d < DD; d += 128) {
        float s = obj[(size_t)bnd * DD + d];
        for (int i = 0; i < cnt; i++) s += obj[(size_t)nb[i] * DD + d];
        gb[d] = s * idn;
    }
    __syncthreads();
    if (t < CC) {
        float a = cls_b[t];
        const float* w = cls_w + (size_t)t * DD;
        for (int d = 0; d < DD; d++) a += gb[d] * w[d];
        lg[t] = a;
    }
    __syncthreads();
    if (t == 0) {
        float mx = lg[0];
        for (int c = 1; c < CC; c++) mx = fmaxf(mx, lg[c]);
        float se = 0.0f;
        for (int c = 0; c < CC; c++) se += expf(lg[c] - mx);
        float ce = mx + logf(se) - lg[CC - 1];
        atomicAdd(&g_sul_sum, (double)ce);
        atomicAdd(&g_nsg, 1);
    }
}

// column / positive sums of exp(S) over matched rows (Sm already holds expS)
__global__ void k_cecred(const int* __restrict__ labels) {
    __shared__ float scol[CC], spos[CC];
    int t = threadIdx.x;
    if (t < CC) { scol[t] = 0.0f; spos[t] = 0.0f; }
    __syncthreads();
    int m = blockIdx.x * 256 + t;
    int M = g_mcnt;
    bool act = m < M;
    int n = act ? g_mlist[m] : 0;
    int lab = act ? labels[n] : 0;
    const float* srow = g_Sm + (size_t)m * CC;
    int lane = t & 31;
    for (int c = 0; c < CC; c++) {
        float e = act ? srow[c] : 0.0f;
        for (int o = 16; o; o >>= 1) e += __shfl_xor_sync(0xffffffffu, e, o);
        if (lane == 0) atomicAdd(&scol[c], e);
    }
    if (act) atomicAdd(&spos[lab], srow[lab]);
    __syncthreads();
    if (t < CC) { atomicAdd(&g_colsum[t], scol[t]); atomicAdd(&g_possum[t], spos[t]); }
}

__global__ void k_pneg() {
    int c2 = blockIdx.x;
    int t = threadIdx.x, lane = t & 31, w = t >> 5;
    const float* pb = g_proto_n + (size_t)c2 * DD;
    __shared__ float acc;
    if (t == 0) acc = 0.0f;
    __syncthreads();
    float local = 0.0f;
    for (int c1 = w; c1 < CC; c1 += 8) {
        if (c1 == c2) continue;
        const float* pa = g_proto_n + (size_t)c1 * DD;
        float d = 0.0f;
#pragma unroll
        for (int i = 0; i < 16; i++) d += pa[lane + i * 32] * pb[lane + i * 32];
        for (int o = 16; o; o >>= 1) d += __shfl_xor_sync(0xffffffffu, d, o);
        if (lane == 0) local += expf(d * 10.0f);
    }
    if (lane == 0) atomicAdd(&acc, local);
    __syncthreads();
    if (t == 0) g_pneg[c2] = acc;
}

__global__ void k_loss(const int* __restrict__ labels) {
    int t = threadIdx.x;
    int m = blockIdx.x * 256 + t;
    float l = 0.0f;
    if (m < g_mcnt) {
        int n = g_mlist[m];
        int lab = labels[n];
        float E = g_pneg[lab] + g_colsum[lab] - g_possum[lab];
        float pe = g_posexp[n];
        l = -logf(pe / (pe + E + 1e-8f));
    }
    for (int o = 16; o; o >>= 1) l += __shfl_xor_sync(0xffffffffu, l, o);
    if ((t & 31) == 0) atomicAdd(&g_cec_sum, (double)l);
}

__global__ void k_fin(float* __restrict__ out) {
    int nsg = g_nsg;
    out[0] = (nsg > 0) ? (float)(g_sul_sum / (double)nsg) : 0.0f;
    int mc = g_mcnt;
    out[1] = (mc > 0) ? (float)(g_cec_sum / (double)mc) : 0.0f;
}

// ---------------- launcher ----------------
extern "C" void kernel_launch(void* const* d_in, const int* in_sizes, int n_in,
                              void* d_out, int out_size) {
    const float* obj    = (const float*)d_in[0];
    const float* protos = (const float*)d_in[1];
    const float* cls_w  = (const float*)d_in[2];
    const float* cls_b  = (const float*)d_in[3];
    const int*   labels = (const int*)d_in[4];
    float* out = (float*)d_out;

    cudaFuncSetAttribute(k_tgemm, cudaFuncAttributeMaxDynamicSharedMemorySize, SMEM_TOTAL_TG);

    k_init<<<1, 256>>>();
    k_proto<<<CC, 128>>>(protos);
    k_rows<<<BQ / 8, 256>>>(obj, labels, protos);
    k_bnd<<<BB * NK / 8, 256>>>(labels);
    k_tgemm<<<dim3(4, 1, BB), 256, SMEM_TOTAL_TG>>>(0);                // SIM + fused top-5
    k_tgemm<<<dim3((BQ + 127) / 128, 1, 1), 256, SMEM_TOTAL_TG>>>(1);  // exp(S)
    k_ce<<<BB * JJ, 128>>>(obj, cls_w, cls_b);
    k_cecred<<<(BQ + 255) / 256, 256>>>(labels);
    k_pneg<<<CC, 256>>>();
    k_loss<<<(BQ + 255) / 256, 256>>>(labels);
    k_fin<<<1, 1>>>(out);
}

// round 8
// speedup vs baseline: 1.1789x; 1.1789x over previous
#include <cuda_runtime.h>
#include <cuda_bf16.h>
#include <math.h>
#include <stdint.h>

#define BB 64
#define QQ 1000
#define DD 512
#define CC 81
#define NK 80
#define KB 5
#define MK 5
#define BQ 64000          // BB*QQ
#define JJ 400            // NK*KB boundary slots per batch
#define DELTA 0.6f
#define INVALID_IDX 0x7fffffff

// ---------------- scratch (device globals; no allocations allowed) ----------------
__device__ uint4 g_embn4[(size_t)BQ * (DD / 8)];     // normalized embeddings, bf16 (65.5 MB)
__device__ uint4 g_protonb4[CC * (DD / 8)];          // normalized prototypes, bf16
__device__ float g_dist2[BQ];
__device__ float g_proto_n[CC * DD];                 // normalized prototypes fp32 (k_pneg)
__device__ float g_p2[NK];
__device__ float g_pinv[CC];
__device__ int   g_mlist[BQ];
__device__ int   g_mcnt;
__device__ int   g_ulist[BB * 1024];
__device__ int   g_ucnt[BB];
__device__ int   g_bnd_gemm[BB * JJ];
__device__ unsigned char g_bnd_valid[BB * JJ];
__device__ float g_SIM[(size_t)BB * JJ * QQ];        // 102.4 MB
__device__ int   g_nb[BB * JJ * MK];
__device__ int   g_nbcnt[BB * JJ];
__device__ unsigned char g_sgv[BB * JJ];
__device__ float g_Sm[(size_t)BQ * CC];              // exp(S) for matched rows (20.7 MB)
__device__ float g_posexp[BQ];                       // fp32-exact pos exp, per row n
__device__ float g_colsum[CC];
__device__ float g_possum[CC];
__device__ float g_pneg[CC];
__device__ double g_sul_sum;
__device__ double g_cec_sum;
__device__ int    g_nsg;

// ---------------- helpers ----------------
__device__ __forceinline__ uint32_t smem_u32(const void* p) {
    uint32_t a;
    asm("{ .reg .u64 t; cvta.to.shared.u64 t, %1; cvt.u32.u64 %0, t; }" : "=r"(a) : "l"(p));
    return a;
}
__device__ __forceinline__ void ldsm_x4(uint32_t& r0, uint32_t& r1, uint32_t& r2, uint32_t& r3,
                                        uint32_t addr) {
    asm volatile("ldmatrix.sync.aligned.m8n8.x4.shared.b16 {%0,%1,%2,%3}, [%4];"
                 : "=r"(r0), "=r"(r1), "=r"(r2), "=r"(r3) : "r"(addr));
}
__device__ __forceinline__ void mma_16816(float* c, const uint32_t* a, uint32_t b0, uint32_t b1) {
    asm volatile(
        "mma.sync.aligned.m16n8k16.row.col.f32.bf16.bf16.f32 "
        "{%0,%1,%2,%3}, {%4,%5,%6,%7}, {%8,%9}, {%0,%1,%2,%3};"
        : "+f"(c[0]), "+f"(c[1]), "+f"(c[2]), "+f"(c[3])
        : "r"(a[0]), "r"(a[1]), "r"(a[2]), "r"(a[3]), "r"(b0), "r"(b1));
}
#define CP16(sm, gm) asm volatile("cp.async.cg.shared.global [%0], [%1], 16;" :: "r"(sm), "l"(gm))
#define CP_COMMIT()  asm volatile("cp.async.commit_group;" ::: "memory")
#define CP_WAIT0()   asm volatile("cp.async.wait_group 0;" ::: "memory")
#define CP_WAIT1()   asm volatile("cp.async.wait_group 1;" ::: "memory")

// ---------------- warp-cooperative top-5 (stable: value desc, index asc) ----------------
__device__ __forceinline__ void lane_ins5(float* v, int* ix, float s, int q) {
    if (s <= v[4]) return;
    int p = 4;
#pragma unroll
    for (int j = 3; j >= 0; j--) if (s > v[j]) p = j;
#pragma unroll
    for (int j = 4; j > 0; j--) if (j > p) { v[j] = v[j - 1]; ix[j] = ix[j - 1]; }
    v[p] = s; ix[p] = q;
}
__device__ __forceinline__ void warp_merge5(float* v, int* ix, float* ov, int* oi) {
#pragma unroll
    for (int r = 0; r < 5; r++) {
        float bv = v[0]; int bi = ix[0];
#pragma unroll
        for (int o = 16; o; o >>= 1) {
            float tv = __shfl_xor_sync(0xffffffffu, bv, o);
            int   ti = __shfl_xor_sync(0xffffffffu, bi, o);
            if (tv > bv || (tv == bv && ti < bi)) { bv = tv; bi = ti; }
        }
        ov[r] = bv; oi[r] = bi;
        if (ix[0] == bi && bi != INVALID_IDX) {
#pragma unroll
            for (int j = 0; j < 4; j++) { v[j] = v[j + 1]; ix[j] = ix[j + 1]; }
            v[4] = -INFINITY; ix[4] = INVALID_IDX;
        }
    }
}

// ---------------- kernels ----------------
// k_proto also performs global init (block 0) — one fewer launch
__global__ void k_proto(const float* __restrict__ protos) {
    int c = blockIdx.x, t = threadIdx.x;
    if (c == 0) {
        if (t == 0) { g_mcnt = 0; g_nsg = 0; g_sul_sum = 0.0; g_cec_sum = 0.0; }
        if (t < BB) g_ucnt[t] = 0;
        if (t < CC) { g_colsum[t] = 0.0f; g_possum[t] = 0.0f; }
    }
    const float* row = protos + (size_t)c * DD;
    float s = 0.0f;
    for (int i = t; i < DD; i += 128) { float v = row[i]; s += v * v; }
    for (int o = 16; o; o >>= 1) s += __shfl_xor_sync(0xffffffffu, s, o);
    __shared__ float ws[4];
    if ((t & 31) == 0) ws[t >> 5] = s;
    __syncthreads();
    __shared__ float sinv;
    if (t == 0) {
        float tot = ws[0] + ws[1] + ws[2] + ws[3];
        if (c < NK) g_p2[c] = tot;
        float inv = 1.0f / fmaxf(sqrtf(tot), 1e-12f);
        g_pinv[c] = inv;
        sinv = inv;
    }
    __syncthreads();
    float inv = sinv;
    const float2* r2 = (const float2*)row;
    uint32_t* pb = (uint32_t*)g_protonb4 + c * (DD / 2);
    for (int i = t; i < DD / 2; i += 128) {
        float2 f = r2[i];
        float x = f.x * inv, y = f.y * inv;
        g_proto_n[c * DD + 2 * i] = x;
        g_proto_n[c * DD + 2 * i + 1] = y;
        __nv_bfloat162 h = __floats2bfloat162_rn(x, y);
        pb[i] = *(uint32_t*)&h;
    }
}

// warp per row: norm, bf16 normalized copy, matched dist + exact fp32 pos_exp, compaction
__global__ void k_rows(const float* __restrict__ obj, const int* __restrict__ labels,
                       const float* __restrict__ protos) {
    int gw = (blockIdx.x * blockDim.x + threadIdx.x) >> 5;
    int lane = threadIdx.x & 31;
    if (gw >= BQ) return;
    const float2* row = (const float2*)(obj + (size_t)gw * DD);
    float2 v[8];
    float s = 0.0f;
#pragma unroll
    for (int i = 0; i < 8; i++) { v[i] = row[lane + 32 * i]; s += v[i].x * v[i].x + v[i].y * v[i].y; }
#pragma unroll
    for (int o = 16; o; o >>= 1) s += __shfl_xor_sync(0xffffffffu, s, o);
    float inv = 1.0f / fmaxf(sqrtf(s), 1e-12f);
    uint32_t* eb = (uint32_t*)g_embn4 + (size_t)gw * (DD / 2);
#pragma unroll
    for (int i = 0; i < 8; i++) {
        __nv_bfloat162 h = __floats2bfloat162_rn(v[i].x * inv, v[i].y * inv);
        eb[lane + 32 * i] = *(uint32_t*)&h;
    }
    int lab = labels[gw];
    if (lab < NK) {
        const float2* pr = (const float2*)(protos + (size_t)lab * DD);
        float d = 0.0f;
#pragma unroll
        for (int i = 0; i < 8; i++) { float2 p = pr[lane + 32 * i]; d += v[i].x * p.x + v[i].y * p.y; }
#pragma unroll
        for (int o = 16; o; o >>= 1) d += __shfl_xor_sync(0xffffffffu, d, o);
        if (lane == 0) {
            g_dist2[gw] = s - 2.0f * d + g_p2[lab];
            g_posexp[gw] = expf(d * inv * g_pinv[lab] * 10.0f);   // exact fp32 S_pos
            int slot = atomicAdd(&g_mcnt, 1);
            g_mlist[slot] = gw;
        }
    } else if (lane == 0) {
        int b = gw / QQ;
        int slot = atomicAdd(&g_ucnt[b], 1);
        g_ulist[b * 1024 + slot] = gw;
    }
}

// warp per (b,k): top-5 matched distances; int4 label loads
__global__ void k_bnd(const int* __restrict__ labels) {
    int gw = (blockIdx.x * blockDim.x + threadIdx.x) >> 5;
    int lane = threadIdx.x & 31;
    if (gw >= BB * NK) return;
    int b = gw / NK, k = gw - b * NK;
    const int4* lb4 = (const int4*)(labels + b * QQ);   // 250 int4s
    const float* dd = g_dist2 + b * QQ;
    float v[5] = {-INFINITY, -INFINITY, -INFINITY, -INFINITY, -INFINITY};
    int ix[5] = {INVALID_IDX, INVALID_IDX, INVALID_IDX, INVALID_IDX, INVALID_IDX};
#pragma unroll
    for (int p = 0; p < 8; p++) {
        int q4 = lane + p * 32;
        if (q4 < 250) {
            int4 L = lb4[q4];
            int qb = q4 * 4;
            if (L.x == k) lane_ins5(v, ix, dd[qb], qb);
            if (L.y == k) lane_ins5(v, ix, dd[qb + 1], qb + 1);
            if (L.z == k) lane_ins5(v, ix, dd[qb + 2], qb + 2);
            if (L.w == k) lane_ins5(v, ix, dd[qb + 3], qb + 3);
        }
    }
    float ov[5]; int oi[5];
    warp_merge5(v, ix, ov, oi);
    if (lane == 0) {
        int base = gw * KB;
#pragma unroll
        for (int i = 0; i < 5; i++) {
            bool valid = oi[i] != INVALID_IDX;
            g_bnd_valid[base + i] = valid ? 1 : 0;
            g_bnd_gemm[base + i] = b * QQ + (valid ? oi[i] : 0);
        }
    }
}

// ---------------- bf16 HMMA gather-GEMM, 128x64 tiles, double-buffered cp.async ----------
// mode 0: SIM[z][m][u] = <embn[bnd], embn[ulist]>        grid (4, 16, 64)
// mode 1: Sm[m][c]     = exp(10 * <embn[mlist], proton>)  grid (ceil(M/128), 2, 1)
// smem: 0 aid[128](512)  512 bid[64](256)
//       1024   A0 128x144 (18432) | B0 64x144 (9216)   = 27648
//       28672  A1 | B1                                  = 27648
//       epilogue sD float[128][66] (33792) aliased at 1024
// total 56320
#define ASTRIDE 144
#define BUFSTRIDE 27648
#define SMEM_TOTAL_TG 56320

__device__ __forceinline__ void tg_prefetch(uint32_t sbase, int buf, int ch,
                                            const uint4* __restrict__ Asrc,
                                            const uint4* __restrict__ Bsrc,
                                            const int* aid, const int* bid, int tid) {
    uint32_t Ab = sbase + 1024 + buf * BUFSTRIDE;
    uint32_t Bb = Ab + 18432;
#pragma unroll
    for (int i = 0; i < 4; i++) {
        int idx = tid + i * 256, r = idx >> 3, j = idx & 7;
        CP16(Ab + r * ASTRIDE + j * 16, Asrc + (size_t)aid[r] * 64 + ch * 8 + j);
    }
#pragma unroll
    for (int i = 0; i < 2; i++) {
        int idx = tid + i * 256, r = idx >> 3, j = idx & 7;
        CP16(Bb + r * ASTRIDE + j * 16, Bsrc + (size_t)bid[r] * 64 + ch * 8 + j);
    }
    CP_COMMIT();
}

__global__ void __launch_bounds__(256) k_tgemm(int mode) {
    extern __shared__ unsigned char smem[];
    const int tid = threadIdx.x, wid = tid >> 5, lid = tid & 31;
    const int wm = wid & 3, wn = wid >> 2;           // warp tile: rows wm*32, cols wn*32
    const int z = blockIdx.z;
    const int m0 = blockIdx.x * 128, n0 = blockIdx.y * 64;
    int M, N;
    const uint4 *Asrc, *Bsrc;
    if (mode == 0) {
        M = JJ; N = g_ucnt[z];
        if (n0 >= N) return;
        Asrc = g_embn4; Bsrc = g_embn4;
    } else {
        M = g_mcnt; N = CC;
        if (m0 >= M) return;
        Asrc = g_embn4; Bsrc = g_protonb4;
    }
    int* aid = (int*)smem;
    int* bid = (int*)(smem + 512);
    uint32_t sbase = smem_u32(smem);
    if (tid < 128) {
        int r = m0 + tid;
        int a;
        if (mode == 0) a = g_bnd_gemm[z * JJ + (r < JJ ? r : 0)];
        else a = (r < M) ? g_mlist[r] : g_mlist[0];
        aid[tid] = a;
    } else if (tid < 192) {
        int c = n0 + tid - 128, b0;
        if (mode == 0) b0 = (c < N) ? g_ulist[z * 1024 + c] : g_ulist[z * 1024];
        else b0 = (c < N) ? c : 0;
        bid[tid - 128] = b0;
    }
    __syncthreads();

    // per-lane ldmatrix address components (buffer 0 base; add buf*BUFSTRIDE)
    const uint32_t As0 = sbase + 1024, Bs0 = sbase + 1024 + 18432;
    uint32_t aAddr = As0 + (uint32_t)(wm * 32 + (lid & 15)) * ASTRIDE + ((lid >> 4) * 8) * 2;
    uint32_t bAddr = Bs0 + (uint32_t)(wn * 32 + ((lid & 7) | ((lid >> 4) << 3))) * ASTRIDE
                         + (((lid >> 3) & 1) * 8) * 2;

    float acc[2][4][4];
#pragma unroll
    for (int i = 0; i < 2; i++)
#pragma unroll
        for (int j = 0; j < 4; j++)
#pragma unroll
            for (int e = 0; e < 4; e++) acc[i][j][e] = 0.0f;

    int buf = 0;
    tg_prefetch(sbase, 0, 0, Asrc, Bsrc, aid, bid, tid);
    for (int ch = 0; ch < 8; ch++) {
        if (ch < 7) {
            tg_prefetch(sbase, buf ^ 1, ch + 1, Asrc, Bsrc, aid, bid, tid);
            CP_WAIT1();
        } else {
            CP_WAIT0();
        }
        __syncthreads();
        uint32_t aA = aAddr + buf * BUFSTRIDE, bA = bAddr + buf * BUFSTRIDE;
#pragma unroll
        for (int ks = 0; ks < 4; ks++) {
            uint32_t a[2][4], b[2][4];
#pragma unroll
            for (int mt = 0; mt < 2; mt++)
                ldsm_x4(a[mt][0], a[mt][1], a[mt][2], a[mt][3],
                        aA + mt * 16 * ASTRIDE + ks * 32);
#pragma unroll
            for (int nh = 0; nh < 2; nh++)
                ldsm_x4(b[nh][0], b[nh][1], b[nh][2], b[nh][3],
                        bA + nh * 16 * ASTRIDE + ks * 32);
#pragma unroll
            for (int mt = 0; mt < 2; mt++)
#pragma unroll
                for (int nt = 0; nt < 4; nt++) {
                    int nh = nt >> 1, hi = (nt & 1) << 1;
                    mma_16816(acc[mt][nt], a[mt], b[nh][hi], b[nh][hi + 1]);
                }
        }
        __syncthreads();   // all ldsm reads of `buf` done before it is refilled
        buf ^= 1;
    }

    if (mode == 0) {
        // transpose through padded smem -> coalesced float2 global stores
        float* sD = (float*)(smem + 1024);     // 128 x 66
#pragma unroll
        for (int mt = 0; mt < 2; mt++)
#pragma unroll
            for (int nt = 0; nt < 4; nt++)
#pragma unroll
                for (int e = 0; e < 4; e++) {
                    int row = wm * 32 + mt * 16 + (lid >> 2) + ((e >> 1) << 3);
                    int col = wn * 32 + nt * 8 + (lid & 3) * 2 + (e & 1);
                    sD[row * 66 + col] = acc[mt][nt][e];
                }
        __syncthreads();
#pragma unroll
        for (int i = 0; i < 16; i++) {
            int idx = tid + i * 256, r = idx >> 5, j = idx & 31;
            int gr = m0 + r, col = n0 + j * 2;
            if (gr < JJ && col < N) {
                float2 val = *(float2*)&sD[r * 66 + j * 2];
                float* dst = g_SIM + ((size_t)(z * JJ + gr)) * QQ + col;
                if (col + 1 < N) *(float2*)dst = val;
                else dst[0] = val.x;
            }
        }
    } else {
        // direct store with fused exp(10*x)
#pragma unroll
        for (int mt = 0; mt < 2; mt++)
#pragma unroll
            for (int nt = 0; nt < 4; nt++)
#pragma unroll
                for (int e = 0; e < 4; e++) {
                    int gr = m0 + wm * 32 + mt * 16 + (lid >> 2) + ((e >> 1) << 3);
                    int col = n0 + wn * 32 + nt * 8 + (lid & 3) * 2 + (e & 1);
                    if (gr < M && col < CC)
                        g_Sm[(size_t)gr * CC + col] = expf(acc[mt][nt][e] * 10.0f);
                }
    }
}

// warp per (b,j): top-5 sims over unmatched, neighbor count, sg_valid
__global__ void k_simtop() {
    int gw = (blockIdx.x * blockDim.x + threadIdx.x) >> 5;
    int lane = threadIdx.x & 31;
    if (gw >= BB * JJ) return;
    int b = gw / JJ;
    const float* srow = g_SIM + (size_t)gw * QQ;
    int U = g_ucnt[b];
    const int* ul = g_ulist + b * 1024;
    float v[5] = {-INFINITY, -INFINITY, -INFINITY, -INFINITY, -INFINITY};
    int ix[5] = {INVALID_IDX, INVALID_IDX, INVALID_IDX, INVALID_IDX, INVALID_IDX};
    for (int u = lane; u < U; u += 32) lane_ins5(v, ix, srow[u], u);
    float ov[5]; int oi[5];
    warp_merge5(v, ix, ov, oi);
    if (lane == 0) {
        int cnt = 0;
        int* nb = g_nb + gw * MK;
#pragma unroll
        for (int i = 0; i < 5; i++) {
            bool valid = oi[i] != INVALID_IDX;
            cnt += (valid && ov[i] > DELTA) ? 1 : 0;
            nb[i] = valid ? ul[oi[i]] : -1;
        }
        g_nbcnt[gw] = cnt;
        g_sgv[gw] = (g_bnd_valid[gw] && cnt > 0) ? 1 : 0;
    }
}

// gated: g_bar -> logits -> CE (expected: no valid slots -> no work)
__global__ void k_ce(const float* __restrict__ obj, const float* __restrict__ cls_w,
                     const float* __restrict__ cls_b) {
    int bj = blockIdx.x;
    if (!g_sgv[bj]) return;
    int t = threadIdx.x;
    __shared__ float gb[DD];
    __shared__ float lg[CC];
    int cnt = g_nbcnt[bj];
    float idn = 1.0f / (1.0f + (float)cnt);
    const int* nb = g_nb + bj * MK;
    int bnd = g_bnd_gemm[bj];
    for (int d = t; d < DD; d += 128) {
        float s = obj[(size_t)bnd * DD + d];
        for (int i = 0; i < cnt; i++) s += obj[(size_t)nb[i] * DD + d];
        gb[d] = s * idn;
    }
    __syncthreads();
    if (t < CC) {
        float a = cls_b[t];
        const float* w = cls_w + (size_t)t * DD;
        for (int d = 0; d < DD; d++) a += gb[d] * w[d];
        lg[t] = a;
    }
    __syncthreads();
    if (t == 0) {
        float mx = lg[0];
        for (int c = 1; c < CC; c++) mx = fmaxf(mx, lg[c]);
        float se = 0.0f;
        for (int c = 0; c < CC; c++) se += expf(lg[c] - mx);
        float ce = mx + logf(se) - lg[CC - 1];
        atomicAdd(&g_sul_sum, (double)ce);
        atomicAdd(&g_nsg, 1);
    }
}

// column / positive sums of exp(S) over matched rows (Sm already holds expS)
__global__ void k_cecred(const int* __restrict__ labels) {
    __shared__ float scol[CC], spos[CC];
    int t = threadIdx.x;
    if (t < CC) { scol[t] = 0.0f; spos[t] = 0.0f; }
    __syncthreads();
    int m = blockIdx.x * 256 + t;
    int M = g_mcnt;
    bool act = m < M;
    int n = act ? g_mlist[m] : 0;
    int lab = act ? labels[n] : 0;
    const float* srow = g_Sm + (size_t)m * CC;
    int lane = t & 31;
    for (int c = 0; c < CC; c++) {
        float e = act ? srow[c] : 0.0f;
        for (int o = 16; o; o >>= 1) e += __shfl_xor_sync(0xffffffffu, e, o);
        if (lane == 0) atomicAdd(&scol[c], e);
    }
    if (act) atomicAdd(&spos[lab], srow[lab]);
    __syncthreads();
    if (t < CC) { atomicAdd(&g_colsum[t], scol[t]); atomicAdd(&g_possum[t], spos[t]); }
}

__global__ void k_pneg() {
    int c2 = blockIdx.x;
    int t = threadIdx.x, lane = t & 31, w = t >> 5;
    const float* pb = g_proto_n + (size_t)c2 * DD;
    __shared__ float acc;
    if (t == 0) acc = 0.0f;
    __syncthreads();
    float local = 0.0f;
    for (int c1 = w; c1 < CC; c1 += 8) {
        if (c1 == c2) continue;
        const float* pa = g_proto_n + (size_t)c1 * DD;
        float d = 0.0f;
#pragma unroll
        for (int i = 0; i < 16; i++) d += pa[lane + i * 32] * pb[lane + i * 32];
        for (int o = 16; o; o >>= 1) d += __shfl_xor_sync(0xffffffffu, d, o);
        if (lane == 0) local += expf(d * 10.0f);
    }
    if (lane == 0) atomicAdd(&acc, local);
    __syncthreads();
    if (t == 0) g_pneg[c2] = acc;
}

__global__ void k_loss(const int* __restrict__ labels) {
    int t = threadIdx.x;
    int m = blockIdx.x * 256 + t;
    float l = 0.0f;
    if (m < g_mcnt) {
        int n = g_mlist[m];
        int lab = labels[n];
        float E = g_pneg[lab] + g_colsum[lab] - g_possum[lab];
        float pe = g_posexp[n];
        l = -logf(pe / (pe + E + 1e-8f));
    }
    for (int o = 16; o; o >>= 1) l += __shfl_xor_sync(0xffffffffu, l, o);
    if ((t & 31) == 0) atomicAdd(&g_cec_sum, (double)l);
}

__global__ void k_fin(float* __restrict__ out) {
    int nsg = g_nsg;
    out[0] = (nsg > 0) ? (float)(g_sul_sum / (double)nsg) : 0.0f;
    int mc = g_mcnt;
    out[1] = (mc > 0) ? (float)(g_cec_sum / (double)mc) : 0.0f;
}

// ---------------- launcher ----------------
extern "C" void kernel_launch(void* const* d_in, const int* in_sizes, int n_in,
                              void* d_out, int out_size) {
    const float* obj    = (const float*)d_in[0];
    const float* protos = (const float*)d_in[1];
    const float* cls_w  = (const float*)d_in[2];
    const float* cls_b  = (const float*)d_in[3];
    const int*   labels = (const int*)d_in[4];
    float* out = (float*)d_out;

    cudaFuncSetAttribute(k_tgemm, cudaFuncAttributeMaxDynamicSharedMemorySize, SMEM_TOTAL_TG);

    k_proto<<<CC, 128>>>(protos);                                      // + init
    k_rows<<<BQ / 8, 256>>>(obj, labels, protos);
    k_bnd<<<BB * NK / 8, 256>>>(labels);
    k_tgemm<<<dim3(4, 16, BB), 256, SMEM_TOTAL_TG>>>(0);               // SIM
    k_tgemm<<<dim3((BQ + 127) / 128, 2, 1), 256, SMEM_TOTAL_TG>>>(1);  // exp(S)
    k_simtop<<<BB * JJ / 8, 256>>>();
    k_ce<<<BB * JJ, 128>>>(obj, cls_w, cls_b);
    k_cecred<<<(BQ + 255) / 256, 256>>>(labels);
    k_pneg<<<CC, 256>>>();
    k_loss<<<(BQ + 255) / 256, 256>>>(labels);
    k_fin<<<1, 1>>>(out);
}